// round 6
// baseline (speedup 1.0000x reference)
#include <cuda_runtime.h>
#include <cstdint>

// VDPDropout fused single-kernel:
//   mu_out    = keep ? mu*1.25 : 0                       [B, H]
//   Sigma_out = 1.5625 * Sigma * (nz_i & nz_j)           [B, H, H]
// Dropped rows are skipped via PREDICATED loads (@P LDG, no branches); groups
// of 4 row-loads issue back-to-back (MLP=4). RPB=32 halves per-block setup
// overhead vs R5. Stores unconditional (output is poisoned).

#define B 32
#define H 2048
#define BH (B * H)              // 65536
#define RPB 32                  // rows per block; 32 | 2048 -> no batch straddle
#define GRID (BH / RPB)         // 2048

// Predicated streaming vec4 load: returns {0,0,0,0} when pred==0, no traffic.
__device__ __forceinline__ float4 ldcs_pred(const float4* p, int pred) {
    float4 v = make_float4(0.f, 0.f, 0.f, 0.f);
    asm volatile(
        "{\n\t.reg .pred p;\n\t"
        "setp.ne.s32 p, %4, 0;\n\t"
        "@p ld.global.cs.v4.f32 {%0,%1,%2,%3}, [%5];\n\t}"
        : "+f"(v.x), "+f"(v.y), "+f"(v.z), "+f"(v.w)
        : "r"(pred), "l"(p));
    return v;
}

__global__ void __launch_bounds__(512)
fused_kernel(const float* __restrict__ mu,
             const unsigned int* __restrict__ mask,
             float* __restrict__ mu_out,
             const float4* __restrict__ Sin,
             float4* __restrict__ Sout) {
    int r0 = blockIdx.x * RPB;          // first row this block owns
    int b  = r0 >> 11;                  // batch index
    __shared__ unsigned char snz[H];

    // ---- mask dtype detection (identical in every block; L2 broadcast) ----
    unsigned int w = (threadIdx.x < 256) ? mask[threadIdx.x] : 0u;
    int bad_i = (threadIdx.x < 256) && (w > 1u);
    int bad_f = (threadIdx.x < 256) && (w != 0u) && (w != 0x3F800000u);
    int any_bad_i = __syncthreads_or(bad_i);
    int any_bad_f = __syncthreads_or(bad_f);
    int kind = !any_bad_i ? 0 : (!any_bad_f ? 1 : 2);

    // ---- recompute this batch's nz row from mu+mask (L2-resident) ----
    int t = threadIdx.x;                // 0..511, 4 elems each = 2048
    float4 mo;
    unsigned char n0, n1, n2, n3;
    {
        float vq[4];
#pragma unroll
        for (int q = 0; q < 4; q++) {
            int gi = b * H + (t << 2) + q;
            bool keep;
            if (kind == 0)      keep = ((const int*)mask)[gi] != 0;
            else if (kind == 1) keep = ((const float*)mask)[gi] != 0.0f;
            else                keep = ((const unsigned char*)mask)[gi] != 0;
            vq[q] = keep ? mu[gi] * 1.25f : 0.0f;
        }
        mo.x = vq[0]; mo.y = vq[1]; mo.z = vq[2]; mo.w = vq[3];
        n0 = vq[0] != 0.0f; n1 = vq[1] != 0.0f;
        n2 = vq[2] != 0.0f; n3 = vq[3] != 0.0f;
    }
    *reinterpret_cast<uchar4*>(snz + (t << 2)) = make_uchar4(n0, n1, n2, n3);

    // one block per batch (the one owning rows [0,RPB)) also writes mu_out
    if ((r0 & (H - 1)) == 0)
        reinterpret_cast<float4*>(mu_out)[b * (H / 4) + t] = mo;
    __syncthreads();

    int j = t << 2;
    bool c0 = snz[j + 0], c1 = snz[j + 1], c2 = snz[j + 2], c3 = snz[j + 3];

    const float4* src = Sin + (size_t)r0 * (H / 4) + t;
    float4*       dst = Sout + (size_t)r0 * (H / 4) + t;
    int rbase = r0 & (H - 1);

    // ---- Sigma stream: groups of 4 rows, predicated loads batched (MLP=4) ----
#pragma unroll
    for (int g = 0; g < RPB; g += 4) {
        int p0 = snz[rbase + g + 0];
        int p1 = snz[rbase + g + 1];
        int p2 = snz[rbase + g + 2];
        int p3 = snz[rbase + g + 3];
        size_t o0 = (size_t)(g + 0) * (H / 4);
        size_t o1 = (size_t)(g + 1) * (H / 4);
        size_t o2 = (size_t)(g + 2) * (H / 4);
        size_t o3 = (size_t)(g + 3) * (H / 4);

        float4 v0 = ldcs_pred(src + o0, p0);
        float4 v1 = ldcs_pred(src + o1, p1);
        float4 v2 = ldcs_pred(src + o2, p2);
        float4 v3 = ldcs_pred(src + o3, p3);

        // v == 0 for dropped rows, so column predicates suffice.
        float4 w0, w1, w2, w3;
        w0.x = c0 ? v0.x * 1.5625f : 0.f; w0.y = c1 ? v0.y * 1.5625f : 0.f;
        w0.z = c2 ? v0.z * 1.5625f : 0.f; w0.w = c3 ? v0.w * 1.5625f : 0.f;
        w1.x = c0 ? v1.x * 1.5625f : 0.f; w1.y = c1 ? v1.y * 1.5625f : 0.f;
        w1.z = c2 ? v1.z * 1.5625f : 0.f; w1.w = c3 ? v1.w * 1.5625f : 0.f;
        w2.x = c0 ? v2.x * 1.5625f : 0.f; w2.y = c1 ? v2.y * 1.5625f : 0.f;
        w2.z = c2 ? v2.z * 1.5625f : 0.f; w2.w = c3 ? v2.w * 1.5625f : 0.f;
        w3.x = c0 ? v3.x * 1.5625f : 0.f; w3.y = c1 ? v3.y * 1.5625f : 0.f;
        w3.z = c2 ? v3.z * 1.5625f : 0.f; w3.w = c3 ? v3.w * 1.5625f : 0.f;

        __stcs(dst + o0, w0);
        __stcs(dst + o1, w1);
        __stcs(dst + o2, w2);
        __stcs(dst + o3, w3);
    }
}

// ---------------------------------------------------------------------------
extern "C" void kernel_launch(void* const* d_in, const int* in_sizes, int n_in,
                              void* d_out, int out_size) {
    const float* mu_in    = (const float*)d_in[0];
    const void*  sigma_in = d_in[1];
    const void*  mask     = d_in[2];

    float* mu_out    = (float*)d_out;
    float* sigma_out = (float*)d_out + BH;

    fused_kernel<<<GRID, 512>>>(mu_in, (const unsigned int*)mask, mu_out,
                                (const float4*)sigma_in, (float4*)sigma_out);
}

// round 7
// speedup vs baseline: 1.0187x; 1.0187x over previous
#include <cuda_runtime.h>
#include <cstdint>

// VDPDropout fused single-kernel (final, = R5 configuration):
//   mu_out    = keep ? mu*1.25 : 0                       [B, H]
//   Sigma_out = 1.5625 * Sigma * (nz_i & nz_j)           [B, H, H]
// Dropped rows are skipped via PREDICATED loads (@P LDG, no branches); groups
// of 4 row-loads issue back-to-back (MLP=4) while dropped rows cost zero read
// traffic. RPB=16 (4096 blocks) is the empirically optimal granularity.

#define B 32
#define H 2048
#define BH (B * H)              // 65536
#define RPB 16                  // rows per block; 16 | 2048 -> no batch straddle
#define GRID (BH / RPB)         // 4096

// Predicated streaming vec4 load: returns {0,0,0,0} when pred==0, no traffic.
__device__ __forceinline__ float4 ldcs_pred(const float4* p, int pred) {
    float4 v = make_float4(0.f, 0.f, 0.f, 0.f);
    asm volatile(
        "{\n\t.reg .pred p;\n\t"
        "setp.ne.s32 p, %4, 0;\n\t"
        "@p ld.global.cs.v4.f32 {%0,%1,%2,%3}, [%5];\n\t}"
        : "+f"(v.x), "+f"(v.y), "+f"(v.z), "+f"(v.w)
        : "r"(pred), "l"(p));
    return v;
}

__global__ void __launch_bounds__(512)
fused_kernel(const float* __restrict__ mu,
             const unsigned int* __restrict__ mask,
             float* __restrict__ mu_out,
             const float4* __restrict__ Sin,
             float4* __restrict__ Sout) {
    int r0 = blockIdx.x * RPB;          // first row this block owns
    int b  = r0 >> 11;                  // batch index
    __shared__ unsigned char snz[H];

    // ---- mask dtype detection (identical in every block; L2 broadcast) ----
    unsigned int w = (threadIdx.x < 256) ? mask[threadIdx.x] : 0u;
    int bad_i = (threadIdx.x < 256) && (w > 1u);
    int bad_f = (threadIdx.x < 256) && (w != 0u) && (w != 0x3F800000u);
    int any_bad_i = __syncthreads_or(bad_i);
    int any_bad_f = __syncthreads_or(bad_f);
    int kind = !any_bad_i ? 0 : (!any_bad_f ? 1 : 2);

    // ---- recompute this batch's nz row from mu+mask (L2-resident) ----
    int t = threadIdx.x;                // 0..511, 4 elems each = 2048
    float4 mo;
    unsigned char n0, n1, n2, n3;
    {
        float vq[4];
#pragma unroll
        for (int q = 0; q < 4; q++) {
            int gi = b * H + (t << 2) + q;
            bool keep;
            if (kind == 0)      keep = ((const int*)mask)[gi] != 0;
            else if (kind == 1) keep = ((const float*)mask)[gi] != 0.0f;
            else                keep = ((const unsigned char*)mask)[gi] != 0;
            vq[q] = keep ? mu[gi] * 1.25f : 0.0f;
        }
        mo.x = vq[0]; mo.y = vq[1]; mo.z = vq[2]; mo.w = vq[3];
        n0 = vq[0] != 0.0f; n1 = vq[1] != 0.0f;
        n2 = vq[2] != 0.0f; n3 = vq[3] != 0.0f;
    }
    *reinterpret_cast<uchar4*>(snz + (t << 2)) = make_uchar4(n0, n1, n2, n3);

    // one block per batch (the one owning rows [0,RPB)) also writes mu_out
    if ((r0 & (H - 1)) == 0)
        reinterpret_cast<float4*>(mu_out)[b * (H / 4) + t] = mo;
    __syncthreads();

    int j = t << 2;
    bool c0 = snz[j + 0], c1 = snz[j + 1], c2 = snz[j + 2], c3 = snz[j + 3];

    const float4* src = Sin + (size_t)r0 * (H / 4) + t;
    float4*       dst = Sout + (size_t)r0 * (H / 4) + t;
    int rbase = r0 & (H - 1);

    // ---- Sigma stream: groups of 4 rows, predicated loads batched (MLP=4) ----
#pragma unroll
    for (int g = 0; g < RPB; g += 4) {
        int p0 = snz[rbase + g + 0];
        int p1 = snz[rbase + g + 1];
        int p2 = snz[rbase + g + 2];
        int p3 = snz[rbase + g + 3];
        size_t o0 = (size_t)(g + 0) * (H / 4);
        size_t o1 = (size_t)(g + 1) * (H / 4);
        size_t o2 = (size_t)(g + 2) * (H / 4);
        size_t o3 = (size_t)(g + 3) * (H / 4);

        float4 v0 = ldcs_pred(src + o0, p0);
        float4 v1 = ldcs_pred(src + o1, p1);
        float4 v2 = ldcs_pred(src + o2, p2);
        float4 v3 = ldcs_pred(src + o3, p3);

        // v == 0 for dropped rows, so column predicates suffice.
        float4 w0, w1, w2, w3;
        w0.x = c0 ? v0.x * 1.5625f : 0.f; w0.y = c1 ? v0.y * 1.5625f : 0.f;
        w0.z = c2 ? v0.z * 1.5625f : 0.f; w0.w = c3 ? v0.w * 1.5625f : 0.f;
        w1.x = c0 ? v1.x * 1.5625f : 0.f; w1.y = c1 ? v1.y * 1.5625f : 0.f;
        w1.z = c2 ? v1.z * 1.5625f : 0.f; w1.w = c3 ? v1.w * 1.5625f : 0.f;
        w2.x = c0 ? v2.x * 1.5625f : 0.f; w2.y = c1 ? v2.y * 1.5625f : 0.f;
        w2.z = c2 ? v2.z * 1.5625f : 0.f; w2.w = c3 ? v2.w * 1.5625f : 0.f;
        w3.x = c0 ? v3.x * 1.5625f : 0.f; w3.y = c1 ? v3.y * 1.5625f : 0.f;
        w3.z = c2 ? v3.z * 1.5625f : 0.f; w3.w = c3 ? v3.w * 1.5625f : 0.f;

        __stcs(dst + o0, w0);
        __stcs(dst + o1, w1);
        __stcs(dst + o2, w2);
        __stcs(dst + o3, w3);
    }
}

// ---------------------------------------------------------------------------
extern "C" void kernel_launch(void* const* d_in, const int* in_sizes, int n_in,
                              void* d_out, int out_size) {
    const float* mu_in    = (const float*)d_in[0];
    const void*  sigma_in = d_in[1];
    const void*  mask     = d_in[2];

    float* mu_out    = (float*)d_out;
    float* sigma_out = (float*)d_out + BH;

    fused_kernel<<<GRID, 512>>>(mu_in, (const unsigned int*)mask, mu_out,
                                (const float4*)sigma_in, (float4*)sigma_out);
}

// round 8
// speedup vs baseline: 1.0218x; 1.0030x over previous
#include <cuda_runtime.h>
#include <cstdint>

// VDPDropout fused single-kernel (RPB=8 fine-grain variant of the R5 optimum):
//   mu_out    = keep ? mu*1.25 : 0                       [B, H]
//   Sigma_out = 1.5625 * Sigma * (nz_i & nz_j)           [B, H, H]
// Dropped rows are skipped via PREDICATED loads (@P LDG, no branches); groups
// of 4 row-loads issue back-to-back (MLP=4) while dropped rows cost zero read
// traffic. Stores unconditional (output is poisoned).

#define B 32
#define H 2048
#define BH (B * H)              // 65536
#define RPB 8                   // rows per block; 8 | 2048 -> no batch straddle
#define GRID (BH / RPB)         // 8192

// Predicated streaming vec4 load: returns {0,0,0,0} when pred==0, no traffic.
__device__ __forceinline__ float4 ldcs_pred(const float4* p, int pred) {
    float4 v = make_float4(0.f, 0.f, 0.f, 0.f);
    asm volatile(
        "{\n\t.reg .pred p;\n\t"
        "setp.ne.s32 p, %4, 0;\n\t"
        "@p ld.global.cs.v4.f32 {%0,%1,%2,%3}, [%5];\n\t}"
        : "+f"(v.x), "+f"(v.y), "+f"(v.z), "+f"(v.w)
        : "r"(pred), "l"(p));
    return v;
}

__global__ void __launch_bounds__(512)
fused_kernel(const float* __restrict__ mu,
             const unsigned int* __restrict__ mask,
             float* __restrict__ mu_out,
             const float4* __restrict__ Sin,
             float4* __restrict__ Sout) {
    int r0 = blockIdx.x * RPB;          // first row this block owns
    int b  = r0 >> 11;                  // batch index
    __shared__ unsigned char snz[H];

    // ---- mask dtype detection (identical in every block; L2 broadcast) ----
    unsigned int w = (threadIdx.x < 256) ? mask[threadIdx.x] : 0u;
    int bad_i = (threadIdx.x < 256) && (w > 1u);
    int bad_f = (threadIdx.x < 256) && (w != 0u) && (w != 0x3F800000u);
    int any_bad_i = __syncthreads_or(bad_i);
    int any_bad_f = __syncthreads_or(bad_f);
    int kind = !any_bad_i ? 0 : (!any_bad_f ? 1 : 2);

    // ---- recompute this batch's nz row from mu+mask (L2-resident) ----
    int t = threadIdx.x;                // 0..511, 4 elems each = 2048
    float4 mo;
    unsigned char n0, n1, n2, n3;
    {
        float vq[4];
#pragma unroll
        for (int q = 0; q < 4; q++) {
            int gi = b * H + (t << 2) + q;
            bool keep;
            if (kind == 0)      keep = ((const int*)mask)[gi] != 0;
            else if (kind == 1) keep = ((const float*)mask)[gi] != 0.0f;
            else                keep = ((const unsigned char*)mask)[gi] != 0;
            vq[q] = keep ? mu[gi] * 1.25f : 0.0f;
        }
        mo.x = vq[0]; mo.y = vq[1]; mo.z = vq[2]; mo.w = vq[3];
        n0 = vq[0] != 0.0f; n1 = vq[1] != 0.0f;
        n2 = vq[2] != 0.0f; n3 = vq[3] != 0.0f;
    }
    *reinterpret_cast<uchar4*>(snz + (t << 2)) = make_uchar4(n0, n1, n2, n3);

    // one block per batch (the one owning rows [0,RPB)) also writes mu_out
    if ((r0 & (H - 1)) == 0)
        reinterpret_cast<float4*>(mu_out)[b * (H / 4) + t] = mo;
    __syncthreads();

    int j = t << 2;
    bool c0 = snz[j + 0], c1 = snz[j + 1], c2 = snz[j + 2], c3 = snz[j + 3];

    const float4* src = Sin + (size_t)r0 * (H / 4) + t;
    float4*       dst = Sout + (size_t)r0 * (H / 4) + t;
    int rbase = r0 & (H - 1);

    // ---- Sigma stream: groups of 4 rows, predicated loads batched (MLP=4) ----
#pragma unroll
    for (int g = 0; g < RPB; g += 4) {
        int p0 = snz[rbase + g + 0];
        int p1 = snz[rbase + g + 1];
        int p2 = snz[rbase + g + 2];
        int p3 = snz[rbase + g + 3];
        size_t o0 = (size_t)(g + 0) * (H / 4);
        size_t o1 = (size_t)(g + 1) * (H / 4);
        size_t o2 = (size_t)(g + 2) * (H / 4);
        size_t o3 = (size_t)(g + 3) * (H / 4);

        float4 v0 = ldcs_pred(src + o0, p0);
        float4 v1 = ldcs_pred(src + o1, p1);
        float4 v2 = ldcs_pred(src + o2, p2);
        float4 v3 = ldcs_pred(src + o3, p3);

        // v == 0 for dropped rows, so column predicates suffice.
        float4 w0, w1, w2, w3;
        w0.x = c0 ? v0.x * 1.5625f : 0.f; w0.y = c1 ? v0.y * 1.5625f : 0.f;
        w0.z = c2 ? v0.z * 1.5625f : 0.f; w0.w = c3 ? v0.w * 1.5625f : 0.f;
        w1.x = c0 ? v1.x * 1.5625f : 0.f; w1.y = c1 ? v1.y * 1.5625f : 0.f;
        w1.z = c2 ? v1.z * 1.5625f : 0.f; w1.w = c3 ? v1.w * 1.5625f : 0.f;
        w2.x = c0 ? v2.x * 1.5625f : 0.f; w2.y = c1 ? v2.y * 1.5625f : 0.f;
        w2.z = c2 ? v2.z * 1.5625f : 0.f; w2.w = c3 ? v2.w * 1.5625f : 0.f;
        w3.x = c0 ? v3.x * 1.5625f : 0.f; w3.y = c1 ? v3.y * 1.5625f : 0.f;
        w3.z = c2 ? v3.z * 1.5625f : 0.f; w3.w = c3 ? v3.w * 1.5625f : 0.f;

        __stcs(dst + o0, w0);
        __stcs(dst + o1, w1);
        __stcs(dst + o2, w2);
        __stcs(dst + o3, w3);
    }
}

// ---------------------------------------------------------------------------
extern "C" void kernel_launch(void* const* d_in, const int* in_sizes, int n_in,
                              void* d_out, int out_size) {
    const float* mu_in    = (const float*)d_in[0];
    const void*  sigma_in = d_in[1];
    const void*  mask     = d_in[2];

    float* mu_out    = (float*)d_out;
    float* sigma_out = (float*)d_out + BH;

    fused_kernel<<<GRID, 512>>>(mu_in, (const unsigned int*)mask, mu_out,
                                (const float4*)sigma_in, (float4*)sigma_out);
}

// round 9
// speedup vs baseline: 1.0337x; 1.0117x over previous
#include <cuda_runtime.h>
#include <cstdint>

// VDPDropout fused single-kernel (RPB=4 finest-grain probe):
//   mu_out    = keep ? mu*1.25 : 0                       [B, H]
//   Sigma_out = 1.5625 * Sigma * (nz_i & nz_j)           [B, H, H]
// Dropped rows skipped via PREDICATED loads (@P LDG, no branches); the whole
// Sigma body is ONE straight-line group of 4 predicated loads (MLP=4), no loop.

#define B 32
#define H 2048
#define BH (B * H)              // 65536
#define RPB 4                   // rows per block; 4 | 2048 -> no batch straddle
#define GRID (BH / RPB)         // 16384

// Predicated streaming vec4 load: returns {0,0,0,0} when pred==0, no traffic.
__device__ __forceinline__ float4 ldcs_pred(const float4* p, int pred) {
    float4 v = make_float4(0.f, 0.f, 0.f, 0.f);
    asm volatile(
        "{\n\t.reg .pred p;\n\t"
        "setp.ne.s32 p, %4, 0;\n\t"
        "@p ld.global.cs.v4.f32 {%0,%1,%2,%3}, [%5];\n\t}"
        : "+f"(v.x), "+f"(v.y), "+f"(v.z), "+f"(v.w)
        : "r"(pred), "l"(p));
    return v;
}

__global__ void __launch_bounds__(512)
fused_kernel(const float* __restrict__ mu,
             const unsigned int* __restrict__ mask,
             float* __restrict__ mu_out,
             const float4* __restrict__ Sin,
             float4* __restrict__ Sout) {
    int r0 = blockIdx.x * RPB;          // first row this block owns
    int b  = r0 >> 11;                  // batch index
    __shared__ unsigned char snz[H];

    // ---- mask dtype detection (identical in every block; L2 broadcast) ----
    unsigned int w = (threadIdx.x < 256) ? mask[threadIdx.x] : 0u;
    int bad_i = (threadIdx.x < 256) && (w > 1u);
    int bad_f = (threadIdx.x < 256) && (w != 0u) && (w != 0x3F800000u);
    int any_bad_i = __syncthreads_or(bad_i);
    int any_bad_f = __syncthreads_or(bad_f);
    int kind = !any_bad_i ? 0 : (!any_bad_f ? 1 : 2);

    // ---- recompute this batch's nz row from mu+mask (L2-resident) ----
    int t = threadIdx.x;                // 0..511, 4 elems each = 2048
    float4 mo;
    unsigned char n0, n1, n2, n3;
    {
        float vq[4];
#pragma unroll
        for (int q = 0; q < 4; q++) {
            int gi = b * H + (t << 2) + q;
            bool keep;
            if (kind == 0)      keep = ((const int*)mask)[gi] != 0;
            else if (kind == 1) keep = ((const float*)mask)[gi] != 0.0f;
            else                keep = ((const unsigned char*)mask)[gi] != 0;
            vq[q] = keep ? mu[gi] * 1.25f : 0.0f;
        }
        mo.x = vq[0]; mo.y = vq[1]; mo.z = vq[2]; mo.w = vq[3];
        n0 = vq[0] != 0.0f; n1 = vq[1] != 0.0f;
        n2 = vq[2] != 0.0f; n3 = vq[3] != 0.0f;
    }
    *reinterpret_cast<uchar4*>(snz + (t << 2)) = make_uchar4(n0, n1, n2, n3);

    // one block per batch (the one owning rows [0,RPB)) also writes mu_out
    if ((r0 & (H - 1)) == 0)
        reinterpret_cast<float4*>(mu_out)[b * (H / 4) + t] = mo;
    __syncthreads();

    int j = t << 2;
    bool c0 = snz[j + 0], c1 = snz[j + 1], c2 = snz[j + 2], c3 = snz[j + 3];

    const float4* src = Sin + (size_t)r0 * (H / 4) + t;
    float4*       dst = Sout + (size_t)r0 * (H / 4) + t;
    int rbase = r0 & (H - 1);

    // ---- Sigma stream: single straight-line group of 4 rows (MLP=4) ----
    int p0 = snz[rbase + 0];
    int p1 = snz[rbase + 1];
    int p2 = snz[rbase + 2];
    int p3 = snz[rbase + 3];
    const size_t o1 = (size_t)1 * (H / 4);
    const size_t o2 = (size_t)2 * (H / 4);
    const size_t o3 = (size_t)3 * (H / 4);

    float4 v0 = ldcs_pred(src, p0);
    float4 v1 = ldcs_pred(src + o1, p1);
    float4 v2 = ldcs_pred(src + o2, p2);
    float4 v3 = ldcs_pred(src + o3, p3);

    // v == 0 for dropped rows, so column predicates suffice.
    float4 w0, w1, w2, w3;
    w0.x = c0 ? v0.x * 1.5625f : 0.f; w0.y = c1 ? v0.y * 1.5625f : 0.f;
    w0.z = c2 ? v0.z * 1.5625f : 0.f; w0.w = c3 ? v0.w * 1.5625f : 0.f;
    w1.x = c0 ? v1.x * 1.5625f : 0.f; w1.y = c1 ? v1.y * 1.5625f : 0.f;
    w1.z = c2 ? v1.z * 1.5625f : 0.f; w1.w = c3 ? v1.w * 1.5625f : 0.f;
    w2.x = c0 ? v2.x * 1.5625f : 0.f; w2.y = c1 ? v2.y * 1.5625f : 0.f;
    w2.z = c2 ? v2.z * 1.5625f : 0.f; w2.w = c3 ? v2.w * 1.5625f : 0.f;
    w3.x = c0 ? v3.x * 1.5625f : 0.f; w3.y = c1 ? v3.y * 1.5625f : 0.f;
    w3.z = c2 ? v3.z * 1.5625f : 0.f; w3.w = c3 ? v3.w * 1.5625f : 0.f;

    __stcs(dst,      w0);
    __stcs(dst + o1, w1);
    __stcs(dst + o2, w2);
    __stcs(dst + o3, w3);
}

// ---------------------------------------------------------------------------
extern "C" void kernel_launch(void* const* d_in, const int* in_sizes, int n_in,
                              void* d_out, int out_size) {
    const float* mu_in    = (const float*)d_in[0];
    const void*  sigma_in = d_in[1];
    const void*  mask     = d_in[2];

    float* mu_out    = (float*)d_out;
    float* sigma_out = (float*)d_out + BH;

    fused_kernel<<<GRID, 512>>>(mu_in, (const unsigned int*)mask, mu_out,
                                (const float4*)sigma_in, (float4*)sigma_out);
}

// round 10
// speedup vs baseline: 1.0366x; 1.0029x over previous
#include <cuda_runtime.h>
#include <cstdint>

// VDPDropout fused single-kernel (RPB=4, streamlined setup):
//   mu_out    = keep ? mu*1.25 : 0                       [B, H]
//   Sigma_out = 1.5625 * Sigma * (nz_i & nz_j)           [B, H, H]
// Column flags live in registers (thread's own n0..n3); only the 4 row
// predicates cross threads (single uchar4 publish). Dropped rows skipped via
// PREDICATED loads (@P LDG); Sigma body is one straight-line MLP=4 group.

#define B 32
#define H 2048
#define BH (B * H)              // 65536
#define RPB 4                   // rows per block; 4 | 2048 -> no batch straddle
#define GRID (BH / RPB)         // 16384

// Predicated streaming vec4 load: returns {0,0,0,0} when pred==0, no traffic.
__device__ __forceinline__ float4 ldcs_pred(const float4* p, int pred) {
    float4 v = make_float4(0.f, 0.f, 0.f, 0.f);
    asm volatile(
        "{\n\t.reg .pred p;\n\t"
        "setp.ne.s32 p, %4, 0;\n\t"
        "@p ld.global.cs.v4.f32 {%0,%1,%2,%3}, [%5];\n\t}"
        : "+f"(v.x), "+f"(v.y), "+f"(v.z), "+f"(v.w)
        : "r"(pred), "l"(p));
    return v;
}

__global__ void __launch_bounds__(512)
fused_kernel(const float* __restrict__ mu,
             const unsigned int* __restrict__ mask,
             float* __restrict__ mu_out,
             const float4* __restrict__ Sin,
             float4* __restrict__ Sout) {
    int r0    = blockIdx.x * RPB;       // first row this block owns
    int b     = r0 >> 11;               // batch index
    int rbase = r0 & (H - 1);           // row offset within batch (4-aligned)
    __shared__ uchar4 s_rowpred;        // nz flags for rows rbase..rbase+3

    // ---- mask dtype detection: ONE combined reduction ----
    unsigned int w = (threadIdx.x < 256) ? mask[threadIdx.x] : 0u;
    int bad = 0;
    if (threadIdx.x < 256) {
        bad  = (w > 1u) ? 1 : 0;                                  // not int32 {0,1}
        bad |= ((w != 0u) && (w != 0x3F800000u)) ? 2 : 0;         // not f32 {0,1.0}
    }
    int anybad = __syncthreads_or(bad);
    int kind = !(anybad & 1) ? 0 : (!(anybad & 2) ? 1 : 2);

    // ---- per-thread: own 4 columns of mu_out / nz (registers only) ----
    int t = threadIdx.x;                // 0..511, 4 elems each = 2048
    float4 mo;
    unsigned char n0, n1, n2, n3;
    {
        float vq[4];
#pragma unroll
        for (int q = 0; q < 4; q++) {
            int gi = b * H + (t << 2) + q;
            bool keep;
            if (kind == 0)      keep = ((const int*)mask)[gi] != 0;
            else if (kind == 1) keep = ((const float*)mask)[gi] != 0.0f;
            else                keep = ((const unsigned char*)mask)[gi] != 0;
            vq[q] = keep ? mu[gi] * 1.25f : 0.0f;
        }
        mo.x = vq[0]; mo.y = vq[1]; mo.z = vq[2]; mo.w = vq[3];
        n0 = vq[0] != 0.0f; n1 = vq[1] != 0.0f;
        n2 = vq[2] != 0.0f; n3 = vq[3] != 0.0f;
    }

    // the thread owning columns rbase..rbase+3 publishes the row predicates
    if (t == (rbase >> 2))
        s_rowpred = make_uchar4(n0, n1, n2, n3);

    // one block per batch (rows [0,RPB)) also writes mu_out
    if (rbase == 0)
        reinterpret_cast<float4*>(mu_out)[b * (H / 4) + t] = mo;
    __syncthreads();

    bool c0 = n0, c1 = n1, c2 = n2, c3 = n3;     // column flags (registers)
    uchar4 rp = s_rowpred;
    int p0 = rp.x, p1 = rp.y, p2 = rp.z, p3 = rp.w;

    const float4* src = Sin + (size_t)r0 * (H / 4) + t;
    float4*       dst = Sout + (size_t)r0 * (H / 4) + t;
    const size_t o1 = (size_t)1 * (H / 4);
    const size_t o2 = (size_t)2 * (H / 4);
    const size_t o3 = (size_t)3 * (H / 4);

    // ---- Sigma stream: single straight-line group of 4 rows (MLP=4) ----
    float4 v0 = ldcs_pred(src,      p0);
    float4 v1 = ldcs_pred(src + o1, p1);
    float4 v2 = ldcs_pred(src + o2, p2);
    float4 v3 = ldcs_pred(src + o3, p3);

    // v == 0 for dropped rows, so column predicates suffice.
    float4 w0, w1, w2, w3;
    w0.x = c0 ? v0.x * 1.5625f : 0.f; w0.y = c1 ? v0.y * 1.5625f : 0.f;
    w0.z = c2 ? v0.z * 1.5625f : 0.f; w0.w = c3 ? v0.w * 1.5625f : 0.f;
    w1.x = c0 ? v1.x * 1.5625f : 0.f; w1.y = c1 ? v1.y * 1.5625f : 0.f;
    w1.z = c2 ? v1.z * 1.5625f : 0.f; w1.w = c3 ? v1.w * 1.5625f : 0.f;
    w2.x = c0 ? v2.x * 1.5625f : 0.f; w2.y = c1 ? v2.y * 1.5625f : 0.f;
    w2.z = c2 ? v2.z * 1.5625f : 0.f; w2.w = c3 ? v2.w * 1.5625f : 0.f;
    w3.x = c0 ? v3.x * 1.5625f : 0.f; w3.y = c1 ? v3.y * 1.5625f : 0.f;
    w3.z = c2 ? v3.z * 1.5625f : 0.f; w3.w = c3 ? v3.w * 1.5625f : 0.f;

    __stcs(dst,      w0);
    __stcs(dst + o1, w1);
    __stcs(dst + o2, w2);
    __stcs(dst + o3, w3);
}

// ---------------------------------------------------------------------------
extern "C" void kernel_launch(void* const* d_in, const int* in_sizes, int n_in,
                              void* d_out, int out_size) {
    const float* mu_in    = (const float*)d_in[0];
    const void*  sigma_in = d_in[1];
    const void*  mask     = d_in[2];

    float* mu_out    = (float*)d_out;
    float* sigma_out = (float*)d_out + BH;

    fused_kernel<<<GRID, 512>>>(mu_in, (const unsigned int*)mask, mu_out,
                                (const float4*)sigma_in, (float4*)sigma_out);
}

// round 11
// speedup vs baseline: 1.0445x; 1.0076x over previous
#include <cuda_runtime.h>
#include <cstdint>

// VDPDropout fused single-kernel (RPB=4, vectorized setup):
//   mu_out    = keep ? mu*1.25 : 0                       [B, H]
//   Sigma_out = 1.5625 * Sigma * (nz_i & nz_j)           [B, H, H]
// Setup reads are vectorized (1x float4 mu + 1x vec4 mask per thread, kind
// branch hoisted). Column flags live in registers; only 4 row-predicate bytes
// cross threads. Dropped rows skipped via PREDICATED loads (@P LDG); Sigma
// body is one straight-line MLP=4 group.

#define B 32
#define H 2048
#define BH (B * H)              // 65536
#define RPB 4                   // rows per block; 4 | 2048 -> no batch straddle
#define GRID (BH / RPB)         // 16384

// Predicated streaming vec4 load: returns {0,0,0,0} when pred==0, no traffic.
__device__ __forceinline__ float4 ldcs_pred(const float4* p, int pred) {
    float4 v = make_float4(0.f, 0.f, 0.f, 0.f);
    asm volatile(
        "{\n\t.reg .pred p;\n\t"
        "setp.ne.s32 p, %4, 0;\n\t"
        "@p ld.global.cs.v4.f32 {%0,%1,%2,%3}, [%5];\n\t}"
        : "+f"(v.x), "+f"(v.y), "+f"(v.z), "+f"(v.w)
        : "r"(pred), "l"(p));
    return v;
}

__global__ void __launch_bounds__(512)
fused_kernel(const float* __restrict__ mu,
             const unsigned int* __restrict__ mask,
             float* __restrict__ mu_out,
             const float4* __restrict__ Sin,
             float4* __restrict__ Sout) {
    int r0    = blockIdx.x * RPB;       // first row this block owns
    int b     = r0 >> 11;               // batch index
    int rbase = r0 & (H - 1);           // row offset within batch (4-aligned)
    __shared__ uchar4 s_rowpred;        // nz flags for rows rbase..rbase+3

    // ---- mask dtype detection: ONE combined reduction ----
    unsigned int w = (threadIdx.x < 256) ? mask[threadIdx.x] : 0u;
    int bad = 0;
    if (threadIdx.x < 256) {
        bad  = (w > 1u) ? 1 : 0;                                  // not int32 {0,1}
        bad |= ((w != 0u) && (w != 0x3F800000u)) ? 2 : 0;         // not f32 {0,1.0}
    }
    int anybad = __syncthreads_or(bad);
    int kind = !(anybad & 1) ? 0 : (!(anybad & 2) ? 1 : 2);

    // ---- per-thread: own 4 columns, VECTORIZED (2 LDGs total) ----
    int t = threadIdx.x;                // 0..511, 4 elems each = 2048
    int v4i = b * (H / 4) + t;          // float4/int4 index of this thread's quad

    float4 muv = reinterpret_cast<const float4*>(mu)[v4i];

    bool k0, k1, k2, k3;
    if (kind == 0) {
        int4 m = reinterpret_cast<const int4*>(mask)[v4i];
        k0 = m.x != 0; k1 = m.y != 0; k2 = m.z != 0; k3 = m.w != 0;
    } else if (kind == 1) {
        float4 m = reinterpret_cast<const float4*>(mask)[v4i];
        k0 = m.x != 0.0f; k1 = m.y != 0.0f; k2 = m.z != 0.0f; k3 = m.w != 0.0f;
    } else {
        uchar4 m = reinterpret_cast<const uchar4*>(mask)[v4i];
        k0 = m.x != 0; k1 = m.y != 0; k2 = m.z != 0; k3 = m.w != 0;
    }

    float4 mo;
    mo.x = k0 ? muv.x * 1.25f : 0.0f;
    mo.y = k1 ? muv.y * 1.25f : 0.0f;
    mo.z = k2 ? muv.z * 1.25f : 0.0f;
    mo.w = k3 ? muv.w * 1.25f : 0.0f;

    unsigned char n0 = mo.x != 0.0f, n1 = mo.y != 0.0f;
    unsigned char n2 = mo.z != 0.0f, n3 = mo.w != 0.0f;

    // the thread owning columns rbase..rbase+3 publishes the row predicates
    if (t == (rbase >> 2))
        s_rowpred = make_uchar4(n0, n1, n2, n3);

    // one block per batch (rows [0,RPB)) also writes mu_out
    if (rbase == 0)
        reinterpret_cast<float4*>(mu_out)[v4i] = mo;
    __syncthreads();

    bool c0 = n0, c1 = n1, c2 = n2, c3 = n3;     // column flags (registers)
    uchar4 rp = s_rowpred;
    int p0 = rp.x, p1 = rp.y, p2 = rp.z, p3 = rp.w;

    const float4* src = Sin + (size_t)r0 * (H / 4) + t;
    float4*       dst = Sout + (size_t)r0 * (H / 4) + t;
    const size_t o1 = (size_t)1 * (H / 4);
    const size_t o2 = (size_t)2 * (H / 4);
    const size_t o3 = (size_t)3 * (H / 4);

    // ---- Sigma stream: single straight-line group of 4 rows (MLP=4) ----
    float4 v0 = ldcs_pred(src,      p0);
    float4 v1 = ldcs_pred(src + o1, p1);
    float4 v2 = ldcs_pred(src + o2, p2);
    float4 v3 = ldcs_pred(src + o3, p3);

    // v == 0 for dropped rows, so column predicates suffice.
    float4 w0, w1, w2, w3;
    w0.x = c0 ? v0.x * 1.5625f : 0.f; w0.y = c1 ? v0.y * 1.5625f : 0.f;
    w0.z = c2 ? v0.z * 1.5625f : 0.f; w0.w = c3 ? v0.w * 1.5625f : 0.f;
    w1.x = c0 ? v1.x * 1.5625f : 0.f; w1.y = c1 ? v1.y * 1.5625f : 0.f;
    w1.z = c2 ? v1.z * 1.5625f : 0.f; w1.w = c3 ? v1.w * 1.5625f : 0.f;
    w2.x = c0 ? v2.x * 1.5625f : 0.f; w2.y = c1 ? v2.y * 1.5625f : 0.f;
    w2.z = c2 ? v2.z * 1.5625f : 0.f; w2.w = c3 ? v2.w * 1.5625f : 0.f;
    w3.x = c0 ? v3.x * 1.5625f : 0.f; w3.y = c1 ? v3.y * 1.5625f : 0.f;
    w3.z = c2 ? v3.z * 1.5625f : 0.f; w3.w = c3 ? v3.w * 1.5625f : 0.f;

    __stcs(dst,      w0);
    __stcs(dst + o1, w1);
    __stcs(dst + o2, w2);
    __stcs(dst + o3, w3);
}

// ---------------------------------------------------------------------------
extern "C" void kernel_launch(void* const* d_in, const int* in_sizes, int n_in,
                              void* d_out, int out_size) {
    const float* mu_in    = (const float*)d_in[0];
    const void*  sigma_in = d_in[1];
    const void*  mask     = d_in[2];

    float* mu_out    = (float*)d_out;
    float* sigma_out = (float*)d_out + BH;

    fused_kernel<<<GRID, 512>>>(mu_in, (const unsigned int*)mask, mu_out,
                                (const float4*)sigma_in, (float4*)sigma_out);
}

// round 12
// speedup vs baseline: 1.0536x; 1.0088x over previous
#include <cuda_runtime.h>
#include <cstdint>

// VDPDropout fused single-kernel (RPB=2 finest-grain probe):
//   mu_out    = keep ? mu*1.25 : 0                       [B, H]
//   Sigma_out = 1.5625 * Sigma * (nz_i & nz_j)           [B, H, H]
// Vectorized setup (1x float4 mu + 1x vec4 mask per thread, kind hoisted).
// Column flags in registers; 2 row-predicate bytes cross threads. Dropped rows
// skipped via PREDICATED loads (@P LDG); straight-line 2-load stream body.

#define B 32
#define H 2048
#define BH (B * H)              // 65536
#define RPB 2                   // rows per block; 2 | 2048 -> no batch straddle
#define GRID (BH / RPB)         // 32768

// Predicated streaming vec4 load: returns {0,0,0,0} when pred==0, no traffic.
__device__ __forceinline__ float4 ldcs_pred(const float4* p, int pred) {
    float4 v = make_float4(0.f, 0.f, 0.f, 0.f);
    asm volatile(
        "{\n\t.reg .pred p;\n\t"
        "setp.ne.s32 p, %4, 0;\n\t"
        "@p ld.global.cs.v4.f32 {%0,%1,%2,%3}, [%5];\n\t}"
        : "+f"(v.x), "+f"(v.y), "+f"(v.z), "+f"(v.w)
        : "r"(pred), "l"(p));
    return v;
}

__global__ void __launch_bounds__(512)
fused_kernel(const float* __restrict__ mu,
             const unsigned int* __restrict__ mask,
             float* __restrict__ mu_out,
             const float4* __restrict__ Sin,
             float4* __restrict__ Sout) {
    int r0    = blockIdx.x * RPB;       // first row this block owns
    int b     = r0 >> 11;               // batch index
    int rbase = r0 & (H - 1);           // row offset within batch (2-aligned)
    __shared__ uchar2 s_rowpred;        // nz flags for rows rbase, rbase+1

    // ---- mask dtype detection: ONE combined reduction ----
    unsigned int w = (threadIdx.x < 256) ? mask[threadIdx.x] : 0u;
    int bad = 0;
    if (threadIdx.x < 256) {
        bad  = (w > 1u) ? 1 : 0;                                  // not int32 {0,1}
        bad |= ((w != 0u) && (w != 0x3F800000u)) ? 2 : 0;         // not f32 {0,1.0}
    }
    int anybad = __syncthreads_or(bad);
    int kind = !(anybad & 1) ? 0 : (!(anybad & 2) ? 1 : 2);

    // ---- per-thread: own 4 columns, VECTORIZED (2 LDGs total) ----
    int t = threadIdx.x;                // 0..511, 4 elems each = 2048
    int v4i = b * (H / 4) + t;          // float4/int4 index of this thread's quad

    float4 muv = reinterpret_cast<const float4*>(mu)[v4i];

    bool k0, k1, k2, k3;
    if (kind == 0) {
        int4 m = reinterpret_cast<const int4*>(mask)[v4i];
        k0 = m.x != 0; k1 = m.y != 0; k2 = m.z != 0; k3 = m.w != 0;
    } else if (kind == 1) {
        float4 m = reinterpret_cast<const float4*>(mask)[v4i];
        k0 = m.x != 0.0f; k1 = m.y != 0.0f; k2 = m.z != 0.0f; k3 = m.w != 0.0f;
    } else {
        uchar4 m = reinterpret_cast<const uchar4*>(mask)[v4i];
        k0 = m.x != 0; k1 = m.y != 0; k2 = m.z != 0; k3 = m.w != 0;
    }

    float4 mo;
    mo.x = k0 ? muv.x * 1.25f : 0.0f;
    mo.y = k1 ? muv.y * 1.25f : 0.0f;
    mo.z = k2 ? muv.z * 1.25f : 0.0f;
    mo.w = k3 ? muv.w * 1.25f : 0.0f;

    unsigned char n0 = mo.x != 0.0f, n1 = mo.y != 0.0f;
    unsigned char n2 = mo.z != 0.0f, n3 = mo.w != 0.0f;

    // the thread owning columns (rbase, rbase+1) publishes the row predicates.
    // rbase is 2-aligned: the pair lives in one thread's quad, halves selected
    // by bit 1 of rbase.
    if (t == (rbase >> 2))
        s_rowpred = (rbase & 2) ? make_uchar2(n2, n3) : make_uchar2(n0, n1);

    // one block per batch (rows [0,RPB)) also writes mu_out
    if (rbase == 0)
        reinterpret_cast<float4*>(mu_out)[v4i] = mo;
    __syncthreads();

    bool c0 = n0, c1 = n1, c2 = n2, c3 = n3;     // column flags (registers)
    uchar2 rp = s_rowpred;
    int p0 = rp.x, p1 = rp.y;

    const float4* src = Sin + (size_t)r0 * (H / 4) + t;
    float4*       dst = Sout + (size_t)r0 * (H / 4) + t;
    const size_t o1 = (size_t)(H / 4);

    // ---- Sigma stream: straight-line pair of rows (MLP=2) ----
    float4 v0 = ldcs_pred(src,      p0);
    float4 v1 = ldcs_pred(src + o1, p1);

    // v == 0 for dropped rows, so column predicates suffice.
    float4 w0, w1;
    w0.x = c0 ? v0.x * 1.5625f : 0.f; w0.y = c1 ? v0.y * 1.5625f : 0.f;
    w0.z = c2 ? v0.z * 1.5625f : 0.f; w0.w = c3 ? v0.w * 1.5625f : 0.f;
    w1.x = c0 ? v1.x * 1.5625f : 0.f; w1.y = c1 ? v1.y * 1.5625f : 0.f;
    w1.z = c2 ? v1.z * 1.5625f : 0.f; w1.w = c3 ? v1.w * 1.5625f : 0.f;

    __stcs(dst,      w0);
    __stcs(dst + o1, w1);
}

// ---------------------------------------------------------------------------
extern "C" void kernel_launch(void* const* d_in, const int* in_sizes, int n_in,
                              void* d_out, int out_size) {
    const float* mu_in    = (const float*)d_in[0];
    const void*  sigma_in = d_in[1];
    const void*  mask     = d_in[2];

    float* mu_out    = (float*)d_out;
    float* sigma_out = (float*)d_out + BH;

    fused_kernel<<<GRID, 512>>>(mu_in, (const unsigned int*)mask, mu_out,
                                (const float4*)sigma_in, (float4*)sigma_out);
}